// round 2
// baseline (speedup 1.0000x reference)
#include <cuda_runtime.h>
#include <cstdint>

// Problem shape (fixed)
#define BB 16
#define TT 2000
#define FF 1024
#define UNROLL 16

__global__ void __launch_bounds__(128, 8)
sa_neuron_kernel(const float* __restrict__ in,
                 float* __restrict__ imem_out,
                 float* __restrict__ spk_out,
                 int write_spikes)
{
    const int tid = blockIdx.x * blockDim.x + threadIdx.x; // 0..16383
    if (tid >= BB * FF) return;
    const int b = tid >> 10;        // /1024
    const int f = tid & (FF - 1);

    // ---- constants: double math exactly as the Python reference, then cast to
    // f32 the way jnp weak-typing casts python floats entering f32 ops ----
    const double tau_s_d = 1e-13 * 0.026 / (0.7 * 2.5e-11);
    const double dt_ms_d = (tau_s_d * 1000.0 / 20.0) > 1e-06 ? (tau_s_d * 1000.0 / 20.0) : 1e-06;
    const float dt_s      = (float)(dt_ms_d * 0.001);
    const float tau_m     = (float)tau_s_d;                               // TAU_M == TAU_S
    const float tau_ahp   = (float)(2.5e-13 * 0.026 / (0.7 * 2e-11));
    const float tau_ref   = (float)(2e-13 * 0.026 / (0.7 * 1.6e-9));
    const float r_gain    = (float)(8.3e-09 / 2.5e-11);                   // 332
    const float z_th      = (float)(5e-10 / 0.19999999999999996);
    const float one_m_a   = (float)(0.19999999999999996);
    const float i_th_ahp  = (float)(1.66e-11);
    const float i_tau_ref = (float)(1.6e-09);
    const float cur_scale = (float)(1e-12);

    const float* __restrict__ ip = in + (size_t)b * TT * FF + f;
    float* __restrict__ im = imem_out + (size_t)b * (TT + 1) * FF + f;
    float* __restrict__ sp = write_spikes ? (spk_out + (size_t)b * (TT + 1) * FF + f)
                                          : nullptr;

    __stcg(im, 0.0f); // imem_trace[:,0,:] = 0; streaming store, don't pollute L2

    float z = 0.0f, i_ahp = 0.0f, i_ref = 0.0f;
    float last_fired = 0.0f;

    float xb[2][UNROLL];

    #pragma unroll
    for (int j = 0; j < UNROLL; ++j)
        xb[0][j] = __ldg(ip + (size_t)j * FF);

    const int NCHUNK = TT / UNROLL; // 125

    #pragma unroll 1
    for (int c = 0; c < NCHUNK; ++c) {
        const int cur = c & 1;
        if (c + 1 < NCHUNK) {
            const float* __restrict__ npx = ip + (size_t)(c + 1) * UNROLL * FF;
            #pragma unroll
            for (int j = 0; j < UNROLL; ++j)
                xb[cur ^ 1][j] = __ldg(npx + (size_t)j * FF);
        }

        const int t0 = c * UNROLL;
        #pragma unroll
        for (int j = 0; j < UNROLL; ++j) {
            // exact reference op order; _rn intrinsics block FMA contraction
            const float i_in  = __fmul_rn(xb[cur][j], cur_scale);
            const float i_net = __fsub_rn(__fsub_rn(i_in, i_ahp), i_ref);
            const float num   = __fadd_rn(-__fmul_rn(one_m_a, z), i_net);
            const float dz_dt = __fdiv_rn(num, tau_m);
            float z_next      = __fadd_rn(z, __fmul_rn(dt_s, dz_dt));
            const bool fired  = (z_next >= z_th);
            z_next = fired ? 0.0f : z_next;

            float ia_n = __fadd_rn(i_ahp, __fmul_rn(dt_s, -__fdiv_rn(i_ahp, tau_ahp)));
            float ir_n = __fadd_rn(i_ref, __fmul_rn(dt_s, -__fdiv_rn(i_ref, tau_ref)));
            if (fired) {
                ia_n = __fadd_rn(ia_n, i_th_ahp);
                ir_n = __fadd_rn(ir_n, i_tau_ref);
            }

            const int t = t0 + j;
            __stcg(im + (size_t)(t + 1) * FF, __fmul_rn(z_next, r_gain));
            const float fval = fired ? 1.0f : 0.0f;
            if (sp) __stcg(sp + (size_t)t * FF, fval);
            last_fired = fval;

            z = z_next; i_ahp = ia_n; i_ref = ir_n;
        }
    }
    if (sp) __stcg(sp + (size_t)TT * FF, last_fired);
}

extern "C" void kernel_launch(void* const* d_in, const int* in_sizes, int n_in,
                              void* d_out, int out_size)
{
    const float* in = (const float*)d_in[0];
    float* out = (float*)d_out;

    const long long N = (long long)BB * (TT + 1) * FF; // 32,784,384 per tensor
    const int write_spikes = ((long long)out_size >= 2 * N) ? 1 : 0;
    float* imem = out;
    float* spk  = write_spikes ? (out + N) : nullptr;

    dim3 grid(128), block(128); // 16384 threads = one per (b,f)
    sa_neuron_kernel<<<grid, block>>>(in, imem, spk, write_spikes);
}

// round 4
// speedup vs baseline: 1.0587x; 1.0587x over previous
#include <cuda_runtime.h>
#include <cstdint>

// Problem shape (fixed)
#define BB 16
#define TT 2000
#define FF 1024
#define UNROLL 16

struct SAState {
    float z, i_ahp, i_ref, last_fired;
};

// Process one 16-step chunk held entirely in registers (statically indexed).
__device__ __forceinline__ void process16(
    const float (&x)[UNROLL], int t0, SAState& s,
    float* __restrict__ im, float* __restrict__ sp,
    float dt_s, float tau_m, float tau_ahp, float tau_ref,
    float r_gain, float z_th, float one_m_a,
    float i_th_ahp, float i_tau_ref, float cur_scale)
{
    float z = s.z, i_ahp = s.i_ahp, i_ref = s.i_ref, last_fired = s.last_fired;
    #pragma unroll
    for (int j = 0; j < UNROLL; ++j) {
        // exact reference op order; _rn intrinsics block FMA contraction
        const float i_in  = __fmul_rn(x[j], cur_scale);
        const float i_net = __fsub_rn(__fsub_rn(i_in, i_ahp), i_ref);
        const float num   = __fadd_rn(-__fmul_rn(one_m_a, z), i_net);
        const float dz_dt = __fdiv_rn(num, tau_m);
        float z_next      = __fadd_rn(z, __fmul_rn(dt_s, dz_dt));
        const bool fired  = (z_next >= z_th);
        z_next = fired ? 0.0f : z_next;

        float ia_n = __fadd_rn(i_ahp, __fmul_rn(dt_s, -__fdiv_rn(i_ahp, tau_ahp)));
        float ir_n = __fadd_rn(i_ref, __fmul_rn(dt_s, -__fdiv_rn(i_ref, tau_ref)));
        if (fired) {
            ia_n = __fadd_rn(ia_n, i_th_ahp);
            ir_n = __fadd_rn(ir_n, i_tau_ref);
        }

        const int t = t0 + j;
        __stcg(im + (size_t)(t + 1) * FF, __fmul_rn(z_next, r_gain));
        const float fval = fired ? 1.0f : 0.0f;
        if (sp) __stcg(sp + (size_t)t * FF, fval);
        last_fired = fval;

        z = z_next; i_ahp = ia_n; i_ref = ir_n;
    }
    s.z = z; s.i_ahp = i_ahp; s.i_ref = i_ref; s.last_fired = last_fired;
}

__device__ __forceinline__ void load16(const float* __restrict__ p, float (&x)[UNROLL])
{
    #pragma unroll
    for (int j = 0; j < UNROLL; ++j)
        x[j] = __ldg(p + (size_t)j * FF);
}

__global__ void __launch_bounds__(128, 4)
sa_neuron_kernel(const float* __restrict__ in,
                 float* __restrict__ imem_out,
                 float* __restrict__ spk_out,
                 int write_spikes)
{
    const int tid = blockIdx.x * blockDim.x + threadIdx.x; // 0..16383
    if (tid >= BB * FF) return;
    const int b = tid >> 10;        // /1024
    const int f = tid & (FF - 1);

    // ---- constants: double math exactly as the Python reference, then cast to
    // f32 the way jnp weak-typing casts python floats entering f32 ops ----
    const double tau_s_d = 1e-13 * 0.026 / (0.7 * 2.5e-11);
    const double dt_ms_d = (tau_s_d * 1000.0 / 20.0) > 1e-06 ? (tau_s_d * 1000.0 / 20.0) : 1e-06;
    const float dt_s      = (float)(dt_ms_d * 0.001);
    const float tau_m     = (float)tau_s_d;                               // TAU_M == TAU_S
    const float tau_ahp   = (float)(2.5e-13 * 0.026 / (0.7 * 2e-11));
    const float tau_ref   = (float)(2e-13 * 0.026 / (0.7 * 1.6e-9));
    const float r_gain    = (float)(8.3e-09 / 2.5e-11);                   // 332
    const float z_th      = (float)(5e-10 / 0.19999999999999996);
    const float one_m_a   = (float)(0.19999999999999996);
    const float i_th_ahp  = (float)(1.66e-11);
    const float i_tau_ref = (float)(1.6e-09);
    const float cur_scale = (float)(1e-12);

    const float* __restrict__ ip = in + (size_t)b * TT * FF + f;
    float* __restrict__ im = imem_out + (size_t)b * (TT + 1) * FF + f;
    float* __restrict__ sp = write_spikes ? (spk_out + (size_t)b * (TT + 1) * FF + f)
                                          : nullptr;

    __stcg(im, 0.0f); // imem_trace[:,0,:] = 0

    SAState s{0.0f, 0.0f, 0.0f, 0.0f};

    float buf0[UNROLL], buf1[UNROLL];   // two STATICALLY-indexed buffers (no spill)

    const int NCHUNK = TT / UNROLL;     // 125 (odd)

    load16(ip, buf0);                   // chunk 0

    // Pairs of chunks: c, c+1 with ping-pong prefetch. Loop covers chunks 0..123.
    #pragma unroll 1
    for (int c = 0; c + 1 < NCHUNK; c += 2) {
        load16(ip + (size_t)(c + 1) * UNROLL * FF, buf1);   // prefetch c+1
        process16(buf0, c * UNROLL, s, im, sp,
                  dt_s, tau_m, tau_ahp, tau_ref, r_gain, z_th, one_m_a,
                  i_th_ahp, i_tau_ref, cur_scale);

        load16(ip + (size_t)(c + 2) * UNROLL * FF, buf0);   // prefetch c+2 (c+2<=124 in-loop)
        process16(buf1, (c + 1) * UNROLL, s, im, sp,
                  dt_s, tau_m, tau_ahp, tau_ref, r_gain, z_th, one_m_a,
                  i_th_ahp, i_tau_ref, cur_scale);
    }

    // Final odd chunk (124), already prefetched into buf0 by the last iteration.
    process16(buf0, (NCHUNK - 1) * UNROLL, s, im, sp,
              dt_s, tau_m, tau_ahp, tau_ref, r_gain, z_th, one_m_a,
              i_th_ahp, i_tau_ref, cur_scale);

    if (sp) __stcg(sp + (size_t)TT * FF, s.last_fired);
}

extern "C" void kernel_launch(void* const* d_in, const int* in_sizes, int n_in,
                              void* d_out, int out_size)
{
    const float* in = (const float*)d_in[0];
    float* out = (float*)d_out;

    const long long N = (long long)BB * (TT + 1) * FF; // 32,784,384 per tensor
    const int write_spikes = ((long long)out_size >= 2 * N) ? 1 : 0;
    float* imem = out;
    float* spk  = write_spikes ? (out + N) : nullptr;

    dim3 grid(128), block(128); // 16384 threads = one per (b,f)
    sa_neuron_kernel<<<grid, block>>>(in, imem, spk, write_spikes);
}

// round 7
// speedup vs baseline: 4.8942x; 4.6229x over previous
#include <cuda_runtime.h>
#include <cstdint>

// Problem shape (fixed)
#define BB 16
#define TT 2000
#define FF 1024
#define UNROLL 16

struct SAState {
    float z, i_ahp, i_ref, last_fired;
};

struct SAConst {
    float dt_s, r_tau_m, r_tau_ahp, r_tau_ref;
    float r_gain, z_th, one_m_a, i_th_ahp, i_tau_ref, cur_scale;
};

// Process one 16-step chunk held entirely in registers (statically indexed).
__device__ __forceinline__ void process16(
    const float (&x)[UNROLL], SAState& s, const SAConst& k,
    float* __restrict__ im,      // -> imem row t0+1
    float* __restrict__ sp)      // -> spike row t0 (or nullptr)
{
    float z = s.z, i_ahp = s.i_ahp, i_ref = s.i_ref, last_fired = s.last_fired;
    #pragma unroll
    for (int j = 0; j < UNROLL; ++j) {
        // reference op order; divides replaced by reciprocal-constant multiplies
        const float i_in  = __fmul_rn(x[j], k.cur_scale);
        const float i_net = __fsub_rn(__fsub_rn(i_in, i_ahp), i_ref);
        const float num   = __fadd_rn(-__fmul_rn(k.one_m_a, z), i_net);
        const float dz_dt = __fmul_rn(num, k.r_tau_m);
        float z_next      = __fadd_rn(z, __fmul_rn(k.dt_s, dz_dt));
        const bool fired  = (z_next >= k.z_th);
        z_next = fired ? 0.0f : z_next;

        float ia_n = __fadd_rn(i_ahp, __fmul_rn(k.dt_s, -__fmul_rn(i_ahp, k.r_tau_ahp)));
        float ir_n = __fadd_rn(i_ref, __fmul_rn(k.dt_s, -__fmul_rn(i_ref, k.r_tau_ref)));
        if (fired) {
            ia_n = __fadd_rn(ia_n, k.i_th_ahp);
            ir_n = __fadd_rn(ir_n, k.i_tau_ref);
        }

        __stcg(im + (size_t)j * FF, __fmul_rn(z_next, k.r_gain));
        const float fval = fired ? 1.0f : 0.0f;
        if (sp) __stcg(sp + (size_t)j * FF, fval);
        last_fired = fval;

        z = z_next; i_ahp = ia_n; i_ref = ir_n;
    }
    s.z = z; s.i_ahp = i_ahp; s.i_ref = i_ref; s.last_fired = last_fired;
}

__device__ __forceinline__ void load16(const float* __restrict__ p, float (&x)[UNROLL])
{
    #pragma unroll
    for (int j = 0; j < UNROLL; ++j)
        x[j] = __ldg(p + (size_t)j * FF);
}

__global__ void __launch_bounds__(128, 4)
sa_neuron_kernel(const float* __restrict__ in,
                 float* __restrict__ imem_out,
                 float* __restrict__ spk_out,
                 int write_spikes)
{
    const int tid = blockIdx.x * blockDim.x + threadIdx.x; // 0..16383
    if (tid >= BB * FF) return;
    const int b = tid >> 10;        // /1024
    const int f = tid & (FF - 1);

    // ---- constants: double math exactly as the Python reference; reciprocals
    // rounded once to f32 (<=1ulp vs __fdiv_rn) ----
    const double tau_m_d   = 1e-13 * 0.026 / (0.7 * 2.5e-11);
    const double tau_ahp_d = 2.5e-13 * 0.026 / (0.7 * 2e-11);
    const double tau_ref_d = 2e-13 * 0.026 / (0.7 * 1.6e-9);
    const double dt_ms_d   = (tau_m_d * 1000.0 / 20.0) > 1e-06 ? (tau_m_d * 1000.0 / 20.0) : 1e-06;

    SAConst k;
    k.dt_s      = (float)(dt_ms_d * 0.001);
    k.r_tau_m   = (float)(1.0 / (double)((float)tau_m_d));    // 1/float(tau) to mimic fp32 divide
    k.r_tau_ahp = (float)(1.0 / (double)((float)tau_ahp_d));
    k.r_tau_ref = (float)(1.0 / (double)((float)tau_ref_d));
    k.r_gain    = (float)(8.3e-09 / 2.5e-11);                  // 332
    k.z_th      = (float)(5e-10 / 0.19999999999999996);
    k.one_m_a   = (float)(0.19999999999999996);
    k.i_th_ahp  = (float)(1.66e-11);
    k.i_tau_ref = (float)(1.6e-09);
    k.cur_scale = (float)(1e-12);

    const float* __restrict__ ip = in + (size_t)b * TT * FF + f;
    float* __restrict__ im = imem_out + (size_t)b * (TT + 1) * FF + f;
    float* __restrict__ sp = write_spikes ? (spk_out + (size_t)b * (TT + 1) * FF + f)
                                          : nullptr;

    __stcg(im, 0.0f); // imem_trace[:,0,:] = 0

    SAState s{0.0f, 0.0f, 0.0f, 0.0f};

    float buf0[UNROLL], buf1[UNROLL];   // statically-indexed double buffer

    const int NCHUNK = TT / UNROLL;     // 125 (odd)
    const size_t CH = (size_t)UNROLL * FF;

    load16(ip, buf0);                   // chunk 0

    const float* lp = ip + CH;          // next chunk to load
    float* imp = im + FF;               // imem row t=1
    float* spp = sp;                    // spike row t=0

    #pragma unroll 1
    for (int c = 0; c + 1 < NCHUNK; c += 2) {
        load16(lp, buf1);  lp += CH;                 // prefetch c+1
        process16(buf0, s, k, imp, spp);
        imp += CH; if (spp) spp += CH;

        load16(lp, buf0);  lp += CH;                 // prefetch c+2 (<=124 in-loop)
        process16(buf1, s, k, imp, spp);
        imp += CH; if (spp) spp += CH;
    }

    // Final odd chunk (124), already in buf0.
    process16(buf0, s, k, imp, spp);

    if (sp) __stcg(sp + (size_t)TT * FF, s.last_fired);
}

extern "C" void kernel_launch(void* const* d_in, const int* in_sizes, int n_in,
                              void* d_out, int out_size)
{
    const float* in = (const float*)d_in[0];
    float* out = (float*)d_out;

    const long long N = (long long)BB * (TT + 1) * FF; // 32,784,384 per tensor
    const int write_spikes = ((long long)out_size >= 2 * N) ? 1 : 0;
    float* imem = out;
    float* spk  = write_spikes ? (out + N) : nullptr;

    dim3 grid(128), block(128); // 16384 threads = one per (b,f)
    sa_neuron_kernel<<<grid, block>>>(in, imem, spk, write_spikes);
}